// round 7
// baseline (speedup 1.0000x reference)
#include <cuda_runtime.h>

// y[..., 2k]   = T[k,0,0]*x[2k] + T[k,0,1]*x[2k+1]
// y[..., 2k+1] = T[k,1,0]*x[2k] + T[k,1,1]*x[2k+1]
// x: (8192 rows, 4096 floats) fp32, twiddle: (2048, 2, 2) fp32.
//
// Column-tiled mapping: each thread owns one 8-float column chunk (4 pairs),
// loads its 16 twiddle floats ONCE into registers, then iterates over 16
// rows (1 LDG.256 + 8 FMA + 1 STG.256 per row). Kills the 2-of-3 load
// instructions that were twiddle refetches; DRAM stream is all that remains.

struct f8 { float v[8]; };

__device__ __forceinline__ f8 ldg256_stream(const float* p) {
    f8 r;
    asm volatile("ld.global.nc.L2::evict_first.v8.b32 "
                 "{%0,%1,%2,%3,%4,%5,%6,%7}, [%8];"
                 : "=f"(r.v[0]), "=f"(r.v[1]), "=f"(r.v[2]), "=f"(r.v[3]),
                   "=f"(r.v[4]), "=f"(r.v[5]), "=f"(r.v[6]), "=f"(r.v[7])
                 : "l"(p));
    return r;
}

__device__ __forceinline__ void stg256_stream(float* p, const f8& r) {
    asm volatile("st.global.L2::evict_first.v8.b32 "
                 "[%0], {%1,%2,%3,%4,%5,%6,%7,%8};"
                 :: "l"(p),
                    "f"(r.v[0]), "f"(r.v[1]), "f"(r.v[2]), "f"(r.v[3]),
                    "f"(r.v[4]), "f"(r.v[5]), "f"(r.v[6]), "f"(r.v[7])
                 : "memory");
}

static constexpr int ROWS_PER_BLOCK = 16;
static constexpr int ROW_FLOATS     = 4096;

__global__ __launch_bounds__(256) void butterfly_kernel(
    const float* __restrict__ x,
    const float* __restrict__ tw,
    float* __restrict__ y)
{
    // blockIdx.x = row_group * 2 + column_half
    const int half  = blockIdx.x & 1;
    const int grp   = blockIdx.x >> 1;
    const int chunk = (half << 8) + threadIdx.x;      // 0..511, 8 floats each
    const int col   = chunk << 3;                      // float offset in row

    // Twiddle for this thread's 4 pairs: floats [16*chunk, 16*chunk+16).
    // Loaded once, reused for all 16 rows.
    const f8 ta = ldg256_stream(&tw[chunk << 4]);
    const f8 tb = ldg256_stream(&tw[(chunk << 4) + 8]);

    const long base = (long)grp * ROWS_PER_BLOCK * ROW_FLOATS + col;

#pragma unroll
    for (int r4 = 0; r4 < ROWS_PER_BLOCK; r4 += 4) {
        f8 v[4];
        // Front-batch 4 independent 256-bit loads (deep MLP).
#pragma unroll
        for (int u = 0; u < 4; u++)
            v[u] = ldg256_stream(&x[base + (long)(r4 + u) * ROW_FLOATS]);

#pragma unroll
        for (int u = 0; u < 4; u++) {
            f8 o;
            o.v[0] = fmaf(ta.v[0], v[u].v[0], ta.v[1] * v[u].v[1]);
            o.v[1] = fmaf(ta.v[2], v[u].v[0], ta.v[3] * v[u].v[1]);
            o.v[2] = fmaf(ta.v[4], v[u].v[2], ta.v[5] * v[u].v[3]);
            o.v[3] = fmaf(ta.v[6], v[u].v[2], ta.v[7] * v[u].v[3]);
            o.v[4] = fmaf(tb.v[0], v[u].v[4], tb.v[1] * v[u].v[5]);
            o.v[5] = fmaf(tb.v[2], v[u].v[4], tb.v[3] * v[u].v[5]);
            o.v[6] = fmaf(tb.v[4], v[u].v[6], tb.v[5] * v[u].v[7]);
            o.v[7] = fmaf(tb.v[6], v[u].v[6], tb.v[7] * v[u].v[7]);
            stg256_stream(&y[base + (long)(r4 + u) * ROW_FLOATS], o);
        }
    }
}

extern "C" void kernel_launch(void* const* d_in, const int* in_sizes, int n_in,
                              void* d_out, int out_size)
{
    const float* x  = (const float*)d_in[0];
    const float* tw = (const float*)d_in[1];
    float* y        = (float*)d_out;

    const int rows   = out_size / ROW_FLOATS;            // 8192
    const int blocks = (rows / ROWS_PER_BLOCK) * 2;      // 1024

    butterfly_kernel<<<blocks, 256>>>(x, tw, y);
}

// round 8
// speedup vs baseline: 1.0610x; 1.0610x over previous
#include <cuda_runtime.h>

// y[..., 2k]   = T[k,0,0]*x[2k] + T[k,0,1]*x[2k+1]
// y[..., 2k+1] = T[k,1,0]*x[2k] + T[k,1,1]*x[2k+1]
// x: (8192 rows, 4096 floats) fp32, twiddle: (2048, 2, 2) fp32 (32 KiB).
//
// Column-tiled: each thread owns one 8-float column chunk (4 pairs), loads
// its 16 twiddle floats ONCE into registers, processes 4 rows (4x reuse).
// ROWS_PER_BLOCK=4 keeps grid at 4096 blocks -> fine scheduling granularity
// (R6's 1024-block grid left ~14% tail imbalance across 148 SMs).

struct f8 { float v[8]; };

__device__ __forceinline__ f8 ldg256_stream(const float* p) {
    f8 r;
    asm volatile("ld.global.nc.L2::evict_first.v8.b32 "
                 "{%0,%1,%2,%3,%4,%5,%6,%7}, [%8];"
                 : "=f"(r.v[0]), "=f"(r.v[1]), "=f"(r.v[2]), "=f"(r.v[3]),
                   "=f"(r.v[4]), "=f"(r.v[5]), "=f"(r.v[6]), "=f"(r.v[7])
                 : "l"(p));
    return r;
}

__device__ __forceinline__ f8 ldg256_cached(const float* p) {
    f8 r;
    asm volatile("ld.global.nc.v8.b32 "
                 "{%0,%1,%2,%3,%4,%5,%6,%7}, [%8];"
                 : "=f"(r.v[0]), "=f"(r.v[1]), "=f"(r.v[2]), "=f"(r.v[3]),
                   "=f"(r.v[4]), "=f"(r.v[5]), "=f"(r.v[6]), "=f"(r.v[7])
                 : "l"(p));
    return r;
}

__device__ __forceinline__ void stg256_stream(float* p, const f8& r) {
    asm volatile("st.global.L2::evict_first.v8.b32 "
                 "[%0], {%1,%2,%3,%4,%5,%6,%7,%8};"
                 :: "l"(p),
                    "f"(r.v[0]), "f"(r.v[1]), "f"(r.v[2]), "f"(r.v[3]),
                    "f"(r.v[4]), "f"(r.v[5]), "f"(r.v[6]), "f"(r.v[7])
                 : "memory");
}

static constexpr int ROWS_PER_BLOCK = 4;
static constexpr int ROW_FLOATS     = 4096;

__global__ __launch_bounds__(256) void butterfly_kernel(
    const float* __restrict__ x,
    const float* __restrict__ tw,
    float* __restrict__ y)
{
    // blockIdx.x = row_group * 2 + column_half
    const int half  = blockIdx.x & 1;
    const int grp   = blockIdx.x >> 1;
    const int chunk = (half << 8) + threadIdx.x;      // 0..511, 8 floats each
    const int col   = chunk << 3;                      // float offset in row

    // Twiddle for this thread's 4 pairs, loaded once (L1/L2-hot, default policy).
    const f8 ta = ldg256_cached(&tw[chunk << 4]);
    const f8 tb = ldg256_cached(&tw[(chunk << 4) + 8]);

    const long base = (long)grp * ROWS_PER_BLOCK * ROW_FLOATS + col;

    f8 v[ROWS_PER_BLOCK];
    // Front-batch all 4 independent 256-bit x loads (deep MLP).
#pragma unroll
    for (int u = 0; u < ROWS_PER_BLOCK; u++)
        v[u] = ldg256_stream(&x[base + (long)u * ROW_FLOATS]);

#pragma unroll
    for (int u = 0; u < ROWS_PER_BLOCK; u++) {
        f8 o;
        o.v[0] = fmaf(ta.v[0], v[u].v[0], ta.v[1] * v[u].v[1]);
        o.v[1] = fmaf(ta.v[2], v[u].v[0], ta.v[3] * v[u].v[1]);
        o.v[2] = fmaf(ta.v[4], v[u].v[2], ta.v[5] * v[u].v[3]);
        o.v[3] = fmaf(ta.v[6], v[u].v[2], ta.v[7] * v[u].v[3]);
        o.v[4] = fmaf(tb.v[0], v[u].v[4], tb.v[1] * v[u].v[5]);
        o.v[5] = fmaf(tb.v[2], v[u].v[4], tb.v[3] * v[u].v[5]);
        o.v[6] = fmaf(tb.v[4], v[u].v[6], tb.v[5] * v[u].v[7]);
        o.v[7] = fmaf(tb.v[6], v[u].v[6], tb.v[7] * v[u].v[7]);
        stg256_stream(&y[base + (long)u * ROW_FLOATS], o);
    }
}

extern "C" void kernel_launch(void* const* d_in, const int* in_sizes, int n_in,
                              void* d_out, int out_size)
{
    const float* x  = (const float*)d_in[0];
    const float* tw = (const float*)d_in[1];
    float* y        = (float*)d_out;

    const int rows   = out_size / ROW_FLOATS;            // 8192
    const int blocks = (rows / ROWS_PER_BLOCK) * 2;      // 4096

    butterfly_kernel<<<blocks, 256>>>(x, tw, y);
}